// round 3
// baseline (speedup 1.0000x reference)
#include <cuda_runtime.h>
#include <math.h>

// ---------------- problem constants ----------------
#define NB    8
#define CCH   256
#define HH    128
#define WW2   128
#define HWP   (HH*WW2)          // 16384
#define TOK0  (NB*HH*WW2)       // 131072 tokens level-0
#define H1    32
#define TOK1  (NB*H1*H1)        // 8192 tokens level-1
#define HEADS 8
#define DH    32
#define DF    1024

// ---------------- device scratch (static; allocation-free) ----------------
__device__ float g_xh   [(size_t)TOK0*CCH];
__device__ float g_q    [(size_t)TOK0*CCH];
__device__ float g_k    [(size_t)TOK0*CCH];
__device__ float g_v    [(size_t)TOK0*CCH];
__device__ float g_attn [(size_t)TOK0*CCH];
__device__ float g_proj [(size_t)TOK0*CCH];
__device__ float g_l0   [(size_t)TOK0*CCH];
__device__ float g_lc   [(size_t)TOK0*CCH];
__device__ float g_hid  [(size_t)TOK0*DF];
__device__ float g_pool [(size_t)TOK1*CCH];
__device__ float g_q1   [(size_t)TOK1*CCH];
__device__ float g_k1   [(size_t)TOK1*CCH];
__device__ float g_v1   [(size_t)TOK1*CCH];
__device__ float g_a1   [(size_t)TOK1*CCH];
__device__ float g_p1   [(size_t)TOK1*CCH];
__device__ float g_l1   [(size_t)TOK1*CCH];

// ---------------- transposes (NCHW <-> NHWC) ----------------
__global__ void transpose_in_k(const float* __restrict__ in, float* __restrict__ out) {
    __shared__ float tile[32][33];
    int n  = blockIdx.z;
    int p0 = blockIdx.x * 32;   // spatial index h*W+w
    int c0 = blockIdx.y * 32;   // channel
    for (int j = threadIdx.y; j < 32; j += 8)
        tile[j][threadIdx.x] = in[((size_t)(n*CCH + c0 + j))*HWP + p0 + threadIdx.x];
    __syncthreads();
    for (int j = threadIdx.y; j < 32; j += 8)
        out[((size_t)(n*HWP + p0 + j))*CCH + c0 + threadIdx.x] = tile[threadIdx.x][j];
}

__global__ void transpose_out_k(const float* __restrict__ in, float* __restrict__ out) {
    __shared__ float tile[32][33];
    int n  = blockIdx.z;
    int p0 = blockIdx.x * 32;
    int c0 = blockIdx.y * 32;
    for (int j = threadIdx.y; j < 32; j += 8)
        tile[j][threadIdx.x] = in[((size_t)(n*HWP + p0 + j))*CCH + c0 + threadIdx.x];
    __syncthreads();
    for (int j = threadIdx.y; j < 32; j += 8)
        out[((size_t)(n*CCH + c0 + j))*HWP + p0 + threadIdx.x] = tile[threadIdx.x][j];
}

// ---------------- tiled fp32 GEMM: C[M,N] = A[M,K] @ B[K,N] (+bias)(+relu) ----
// BM=BN=64, BK=16, 256 threads, 4x4 register tile per thread.
template<bool RELU, bool BIAS>
__global__ void gemm64_k(const float* __restrict__ A, const float* __restrict__ B,
                         const float* __restrict__ bias, float* __restrict__ C,
                         int M, int N, int K) {
    __shared__ float As[16][65];   // [k][m], padded
    __shared__ float Bs[16][64];   // [k][n]
    int tid = threadIdx.x;
    int m0 = blockIdx.y * 64, n0 = blockIdx.x * 64;
    int ty = tid >> 4, tx = tid & 15;
    float acc[4][4] = {};
    const float* Ab = A + (size_t)m0 * K;
    const float* Bb = B + n0;

    for (int k0 = 0; k0 < K; k0 += 16) {
        {   // load A 64x16 (one float4/thread)
            int m  = tid >> 2;
            int k4 = (tid & 3) * 4;
            float4 a = *(const float4*)&Ab[(size_t)m*K + k0 + k4];
            As[k4+0][m] = a.x; As[k4+1][m] = a.y; As[k4+2][m] = a.z; As[k4+3][m] = a.w;
        }
        {   // load B 16x64 (one float4/thread)
            int k  = tid >> 4;
            int n4 = (tid & 15) * 4;
            float4 b = *(const float4*)&Bb[(size_t)(k0+k)*N + n4];
            *(float4*)&Bs[k][n4] = b;
        }
        __syncthreads();
        #pragma unroll
        for (int kk = 0; kk < 16; kk++) {
            float a[4], b[4];
            #pragma unroll
            for (int j = 0; j < 4; j++) a[j] = As[kk][ty + 16*j];
            #pragma unroll
            for (int i = 0; i < 4; i++) b[i] = Bs[kk][tx + 16*i];
            #pragma unroll
            for (int j = 0; j < 4; j++)
                #pragma unroll
                for (int i = 0; i < 4; i++)
                    acc[j][i] += a[j] * b[i];
        }
        __syncthreads();
    }
    #pragma unroll
    for (int j = 0; j < 4; j++) {
        size_t m = m0 + ty + 16*j;
        #pragma unroll
        for (int i = 0; i < 4; i++) {
            int n = n0 + tx + 16*i;
            float v = acc[j][i];
            if (BIAS) v += bias[n];
            if (RELU) v = fmaxf(v, 0.f);
            C[m*N + n] = v;
        }
    }
}

// ---------------- fused windowed attention -----------------------------
// One block = (window, head). 64 threads = 64 query tokens.
// Handles self-attention (strideK=8, kv grid == q grid) and stride-2
// circular cross-attention (strideK=2, kv grid 32x32).
__global__ void attn_win_k(const float* __restrict__ Q, const float* __restrict__ K,
                           const float* __restrict__ V, float* __restrict__ O,
                           int Hq, int Wq, int Hk, int Wk, int strideK) {
    int wW = Wq >> 3, wH = Hq >> 3;
    int b    = blockIdx.x;
    int head = blockIdx.y;
    int ww = b % wW; int t1 = b / wW;
    int wh = t1 % wH; int n  = t1 / wH;
    int t = threadIdx.x;

    __shared__ float Ks[64][33];
    __shared__ float Vs[64][33];

    // load K/V token t of this window's kv patch
    {
        int ki = t >> 3, kj = t & 7;
        int rk = (wh * strideK + ki) % Hk;
        int ck = (ww * strideK + kj) % Wk;
        size_t kb = ((size_t)(n*Hk + rk)*Wk + ck) * CCH + head*DH;
        #pragma unroll
        for (int c = 0; c < DH; c += 4) {
            float4 kk4 = *(const float4*)&K[kb + c];
            Ks[t][c] = kk4.x; Ks[t][c+1] = kk4.y; Ks[t][c+2] = kk4.z; Ks[t][c+3] = kk4.w;
            float4 vv4 = *(const float4*)&V[kb + c];
            Vs[t][c] = vv4.x; Vs[t][c+1] = vv4.y; Vs[t][c+2] = vv4.z; Vs[t][c+3] = vv4.w;
        }
    }
    // Q row for this query token
    int rq = wh*8 + (t >> 3), cq = ww*8 + (t & 7);
    size_t qb = ((size_t)(n*Hq + rq)*Wq + cq) * CCH + head*DH;
    float q[DH];
    #pragma unroll
    for (int c = 0; c < DH; c++) q[c] = Q[qb + c];
    __syncthreads();

    const float scale = 0.17677669529663687f;  // 1/sqrt(32)
    float s[64];
    float mx = -1e30f;
    #pragma unroll
    for (int j = 0; j < 64; j++) {
        float d = 0.f;
        #pragma unroll
        for (int c = 0; c < DH; c++) d += q[c] * Ks[j][c];
        d *= scale;
        s[j] = d;
        mx = fmaxf(mx, d);
    }
    float sum = 0.f;
    #pragma unroll
    for (int j = 0; j < 64; j++) { s[j] = __expf(s[j] - mx); sum += s[j]; }
    float inv = 1.f / sum;
    #pragma unroll
    for (int c = 0; c < DH; c++) {
        float acc = 0.f;
        #pragma unroll
        for (int j = 0; j < 64; j++) acc += s[j] * Vs[j][c];
        O[qb + c] = acc * inv;
    }
}

// ---------------- fused residual-add + layernorm (C=256) -----------------
__global__ void add_ln_k(const float* __restrict__ X, const float* __restrict__ P,
                         const float* __restrict__ g, const float* __restrict__ b,
                         float* __restrict__ out) {
    int tok = blockIdx.x;
    int c   = threadIdx.x;
    size_t idx = (size_t)tok * CCH + c;
    float v = X[idx] + P[idx];

    __shared__ float red[8];
    float s = v;
    #pragma unroll
    for (int o = 16; o; o >>= 1) s += __shfl_xor_sync(0xffffffffu, s, o);
    if ((c & 31) == 0) red[c >> 5] = s;
    __syncthreads();
    float mu = 0.f;
    #pragma unroll
    for (int i = 0; i < 8; i++) mu += red[i];
    mu *= (1.f / CCH);

    float d  = v - mu;
    float s2 = d * d;
    #pragma unroll
    for (int o = 16; o; o >>= 1) s2 += __shfl_xor_sync(0xffffffffu, s2, o);
    __syncthreads();
    if ((c & 31) == 0) red[c >> 5] = s2;
    __syncthreads();
    float var = 0.f;
    #pragma unroll
    for (int i = 0; i < 8; i++) var += red[i];
    var *= (1.f / CCH);

    out[idx] = d * rsqrtf(var + 1e-5f) * g[c] + b[c];
}

// ---------------- 4x4 average pool (128x128 -> 32x32) --------------------
__global__ void avgpool_k(const float* __restrict__ in, float* __restrict__ out) {
    int i = blockIdx.x * blockDim.x + threadIdx.x;
    if (i >= TOK1 * CCH) return;
    int c    = i & (CCH - 1);
    int toko = i >> 8;
    int ow = toko & 31; int t = toko >> 5;
    int oh = t & 31;    int n = t >> 5;
    float s = 0.f;
    #pragma unroll
    for (int di = 0; di < 4; di++)
        #pragma unroll
        for (int dj = 0; dj < 4; dj++)
            s += in[((size_t)(n*HH + oh*4 + di)*WW2 + ow*4 + dj)*CCH + c];
    out[i] = s * (1.f / 16.f);
}

// ---------------- host orchestration -------------------------------------
static inline void run_gemm(const float* A, const float* B, const float* bias,
                            float* C, int M, int N, int K, bool relu) {
    dim3 grid(N / 64, M / 64);
    if (relu)       gemm64_k<true,  true ><<<grid, 256>>>(A, B, bias, C, M, N, K);
    else if (bias)  gemm64_k<false, true ><<<grid, 256>>>(A, B, bias, C, M, N, K);
    else            gemm64_k<false, false><<<grid, 256>>>(A, B, bias, C, M, N, K);
}

extern "C" void kernel_launch(void* const* d_in, const int* in_sizes, int n_in,
                              void* d_out, int out_size) {
    const float* x        = (const float*)d_in[0];
    const float* sa_wq    = (const float*)d_in[1];
    const float* sa_wk    = (const float*)d_in[2];
    const float* sa_wv    = (const float*)d_in[3];
    const float* sa_wf    = (const float*)d_in[4];
    const float* sa_bf    = (const float*)d_in[5];
    const float* ca_wq    = (const float*)d_in[6];
    const float* ca_wk    = (const float*)d_in[7];
    const float* ca_wv    = (const float*)d_in[8];
    const float* ca_wf    = (const float*)d_in[9];
    const float* ca_bf    = (const float*)d_in[10];
    const float* ln_s_g   = (const float*)d_in[11];
    const float* ln_s_b   = (const float*)d_in[12];
    const float* ln_c_g   = (const float*)d_in[13];
    const float* ln_c_b   = (const float*)d_in[14];
    const float* ffn_w1   = (const float*)d_in[15];
    const float* ffn_b1   = (const float*)d_in[16];
    const float* ffn_w2   = (const float*)d_in[17];
    const float* ffn_b2   = (const float*)d_in[18];
    const float* ln_o_g   = (const float*)d_in[19];
    const float* ln_o_b   = (const float*)d_in[20];

    float *xh, *q, *k, *v, *attn, *proj, *l0, *lc, *hid;
    float *pool, *q1, *k1, *v1, *a1, *p1, *l1;
    cudaGetSymbolAddress((void**)&xh,   g_xh);
    cudaGetSymbolAddress((void**)&q,    g_q);
    cudaGetSymbolAddress((void**)&k,    g_k);
    cudaGetSymbolAddress((void**)&v,    g_v);
    cudaGetSymbolAddress((void**)&attn, g_attn);
    cudaGetSymbolAddress((void**)&proj, g_proj);
    cudaGetSymbolAddress((void**)&l0,   g_l0);
    cudaGetSymbolAddress((void**)&lc,   g_lc);
    cudaGetSymbolAddress((void**)&hid,  g_hid);
    cudaGetSymbolAddress((void**)&pool, g_pool);
    cudaGetSymbolAddress((void**)&q1,   g_q1);
    cudaGetSymbolAddress((void**)&k1,   g_k1);
    cudaGetSymbolAddress((void**)&v1,   g_v1);
    cudaGetSymbolAddress((void**)&a1,   g_a1);
    cudaGetSymbolAddress((void**)&p1,   g_p1);
    cudaGetSymbolAddress((void**)&l1,   g_l1);

    dim3 tb(32, 8);
    // NCHW -> NHWC
    transpose_in_k<<<dim3(HWP/32, CCH/32, NB), tb>>>(x, xh);

    // ---- level-0 self-attention (128x128) ----
    run_gemm(xh, sa_wq, nullptr, q, TOK0, CCH, CCH, false);
    run_gemm(xh, sa_wk, nullptr, k, TOK0, CCH, CCH, false);
    run_gemm(xh, sa_wv, nullptr, v, TOK0, CCH, CCH, false);
    attn_win_k<<<dim3(NB*16*16, HEADS), 64>>>(q, k, v, attn, HH, WW2, HH, WW2, 8);
    run_gemm(attn, sa_wf, sa_bf, proj, TOK0, CCH, CCH, false);
    add_ln_k<<<TOK0, CCH>>>(xh, proj, ln_s_g, ln_s_b, l0);

    // ---- pool to 32x32 ----
    avgpool_k<<<(TOK1*CCH + 255)/256, 256>>>(l0, pool);

    // ---- level-1 self-attention (32x32) ----
    run_gemm(pool, sa_wq, nullptr, q1, TOK1, CCH, CCH, false);
    run_gemm(pool, sa_wk, nullptr, k1, TOK1, CCH, CCH, false);
    run_gemm(pool, sa_wv, nullptr, v1, TOK1, CCH, CCH, false);
    attn_win_k<<<dim3(NB*4*4, HEADS), 64>>>(q1, k1, v1, a1, H1, H1, H1, H1, 8);
    run_gemm(a1, sa_wf, sa_bf, p1, TOK1, CCH, CCH, false);
    add_ln_k<<<TOK1, CCH>>>(pool, p1, ln_s_g, ln_s_b, l1);

    // ---- cross-attention: q = l0 (128x128), kv = l1 (32x32, stride-2 circular)
    run_gemm(l0, ca_wq, nullptr, q,  TOK0, CCH, CCH, false);
    run_gemm(l1, ca_wk, nullptr, k1, TOK1, CCH, CCH, false);
    run_gemm(l1, ca_wv, nullptr, v1, TOK1, CCH, CCH, false);
    attn_win_k<<<dim3(NB*16*16, HEADS), 64>>>(q, k1, v1, attn, HH, WW2, H1, H1, 2);
    run_gemm(attn, ca_wf, ca_bf, proj, TOK0, CCH, CCH, false);
    add_ln_k<<<TOK0, CCH>>>(l0, proj, ln_c_g, ln_c_b, lc);

    // ---- FFN 256 -> 1024 (relu) -> 256, then residual + LN ----
    run_gemm(lc,  ffn_w1, ffn_b1, hid,  TOK0, DF,  CCH, true);
    run_gemm(hid, ffn_w2, ffn_b2, proj, TOK0, CCH, DF,  false);
    add_ln_k<<<TOK0, CCH>>>(lc, proj, ln_o_g, ln_o_b, attn);

    // NHWC -> NCHW
    transpose_out_k<<<dim3(HWP/32, CCH/32, NB), tb>>>(attn, (float*)d_out);
}

// round 7
// speedup vs baseline: 1.4019x; 1.4019x over previous
#include <cuda_runtime.h>
#include <math.h>

// ---------------- problem constants ----------------
#define NB    8
#define CCH   256
#define HH    128
#define WW2   128
#define HWP   (HH*WW2)          // 16384
#define TOK0  (NB*HH*WW2)       // 131072 tokens level-0
#define H1    32
#define TOK1  (NB*H1*H1)        // 8192 tokens level-1
#define HEADS 8
#define DH    32
#define DF    1024

// ---------------- device scratch (static; allocation-free) ----------------
__device__ float g_xh   [(size_t)TOK0*CCH];
__device__ float g_q    [(size_t)TOK0*CCH];
__device__ float g_k    [(size_t)TOK0*CCH];
__device__ float g_v    [(size_t)TOK0*CCH];
__device__ float g_attn [(size_t)TOK0*CCH];
__device__ float g_proj [(size_t)TOK0*CCH];
__device__ float g_l0   [(size_t)TOK0*CCH];
__device__ float g_lc   [(size_t)TOK0*CCH];
__device__ float g_hid  [(size_t)TOK0*DF];
__device__ float g_pool [(size_t)TOK1*CCH];
__device__ float g_q1   [(size_t)TOK1*CCH];
__device__ float g_k1   [(size_t)TOK1*CCH];
__device__ float g_v1   [(size_t)TOK1*CCH];
__device__ float g_a1   [(size_t)TOK1*CCH];
__device__ float g_p1   [(size_t)TOK1*CCH];
__device__ float g_l1   [(size_t)TOK1*CCH];

// ---------------- transposes (NCHW <-> NHWC) ----------------
__global__ void transpose_in_k(const float* __restrict__ in, float* __restrict__ out) {
    __shared__ float tile[32][33];
    int n  = blockIdx.z;
    int p0 = blockIdx.x * 32;   // spatial index h*W+w
    int c0 = blockIdx.y * 32;   // channel
    for (int j = threadIdx.y; j < 32; j += 8)
        tile[j][threadIdx.x] = in[((size_t)(n*CCH + c0 + j))*HWP + p0 + threadIdx.x];
    __syncthreads();
    for (int j = threadIdx.y; j < 32; j += 8)
        out[((size_t)(n*HWP + p0 + j))*CCH + c0 + threadIdx.x] = tile[threadIdx.x][j];
}

__global__ void transpose_out_k(const float* __restrict__ in, float* __restrict__ out) {
    __shared__ float tile[32][33];
    int n  = blockIdx.z;
    int p0 = blockIdx.x * 32;
    int c0 = blockIdx.y * 32;
    for (int j = threadIdx.y; j < 32; j += 8)
        tile[j][threadIdx.x] = in[((size_t)(n*HWP + p0 + j))*CCH + c0 + threadIdx.x];
    __syncthreads();
    for (int j = threadIdx.y; j < 32; j += 8)
        out[((size_t)(n*CCH + c0 + j))*HWP + p0 + threadIdx.x] = tile[threadIdx.x][j];
}

// ---------------- tiled fp32 GEMM: C[M,N] = A[M,K] @ B[K,N] (+bias)(+relu) ----
// BM=BN=128, BK=16, 256 threads, 8x8 register tile per thread, LDS.128 only,
// register prefetch of next global tile. Requires M%128==0, N%128==0, K%16==0.
template<bool RELU, bool BIAS>
__global__ __launch_bounds__(256, 2)
void gemm128_k(const float* __restrict__ A, const float* __restrict__ B,
               const float* __restrict__ bias, float* __restrict__ C,
               int M, int N, int K) {
    __shared__ float As[16][132];   // [k][m] (transposed), stride 132 -> 528B rows (16B aligned)
    __shared__ float Bs[16][128];   // [k][n]
    int tid = threadIdx.x;
    int m0 = blockIdx.y * 128, n0 = blockIdx.x * 128;
    int ty = tid >> 4, tx = tid & 15;

    // A tile load mapping: 128x16 floats = 512 float4; thread covers rows ar and ar+64
    int ar = tid >> 2;            // 0..63
    int ak = (tid & 3) * 4;       // 0,4,8,12
    // B tile load mapping: 16x128 floats = 512 float4; rows br and br+8
    int br = tid >> 5;            // 0..7
    int bc = (tid & 31) * 4;      // 0..124

    const float* Aptr = A + (size_t)(m0 + ar) * K + ak;
    const float* Bptr = B + (size_t)br * N + n0 + bc;
    const size_t a64 = (size_t)64 * K;
    const size_t b8  = (size_t)8 * N;

    float acc[8][8] = {};

    float4 pa0 = *(const float4*)(Aptr);
    float4 pa1 = *(const float4*)(Aptr + a64);
    float4 pb0 = *(const float4*)(Bptr);
    float4 pb1 = *(const float4*)(Bptr + b8);

    for (int k0 = 0; k0 < K; k0 += 16) {
        // stage to smem (A transposed)
        As[ak+0][ar] = pa0.x; As[ak+1][ar] = pa0.y; As[ak+2][ar] = pa0.z; As[ak+3][ar] = pa0.w;
        As[ak+0][ar+64] = pa1.x; As[ak+1][ar+64] = pa1.y; As[ak+2][ar+64] = pa1.z; As[ak+3][ar+64] = pa1.w;
        *(float4*)&Bs[br][bc]   = pb0;
        *(float4*)&Bs[br+8][bc] = pb1;
        __syncthreads();

        if (k0 + 16 < K) {   // prefetch next tile into registers
            Aptr += 16;
            Bptr += (size_t)16 * N;
            pa0 = *(const float4*)(Aptr);
            pa1 = *(const float4*)(Aptr + a64);
            pb0 = *(const float4*)(Bptr);
            pb1 = *(const float4*)(Bptr + b8);
        }

        #pragma unroll
        for (int kk = 0; kk < 16; kk++) {
            float4 a0 = *(const float4*)&As[kk][ty*4];
            float4 a1 = *(const float4*)&As[kk][ty*4 + 64];
            float4 b0 = *(const float4*)&Bs[kk][tx*4];
            float4 b1 = *(const float4*)&Bs[kk][tx*4 + 64];
            float a[8] = {a0.x, a0.y, a0.z, a0.w, a1.x, a1.y, a1.z, a1.w};
            float b[8] = {b0.x, b0.y, b0.z, b0.w, b1.x, b1.y, b1.z, b1.w};
            #pragma unroll
            for (int i = 0; i < 8; i++)
                #pragma unroll
                for (int j = 0; j < 8; j++)
                    acc[i][j] += a[i] * b[j];
        }
        __syncthreads();
    }

    // epilogue
    #pragma unroll
    for (int i = 0; i < 8; i++) {
        int mi = (i < 4) ? (ty*4 + i) : (64 + ty*4 + (i-4));
        size_t m = (size_t)(m0 + mi);
        #pragma unroll
        for (int j = 0; j < 8; j++) {
            int nj = (j < 4) ? (tx*4 + j) : (64 + tx*4 + (j-4));
            int n = n0 + nj;
            float v = acc[i][j];
            if (BIAS) v += bias[n];
            if (RELU) v = fmaxf(v, 0.f);
            C[m*N + n] = v;
        }
    }
}

// ---------------- fused windowed attention -----------------------------
__global__ void attn_win_k(const float* __restrict__ Q, const float* __restrict__ K,
                           const float* __restrict__ V, float* __restrict__ O,
                           int Hq, int Wq, int Hk, int Wk, int strideK) {
    int wW = Wq >> 3, wH = Hq >> 3;
    int b    = blockIdx.x;
    int head = blockIdx.y;
    int ww = b % wW; int t1 = b / wW;
    int wh = t1 % wH; int n  = t1 / wH;
    int t = threadIdx.x;

    __shared__ float Ks[64][33];
    __shared__ float Vs[64][33];

    {
        int ki = t >> 3, kj = t & 7;
        int rk = (wh * strideK + ki) % Hk;
        int ck = (ww * strideK + kj) % Wk;
        size_t kb = ((size_t)(n*Hk + rk)*Wk + ck) * CCH + head*DH;
        #pragma unroll
        for (int c = 0; c < DH; c += 4) {
            float4 kk4 = *(const float4*)&K[kb + c];
            Ks[t][c] = kk4.x; Ks[t][c+1] = kk4.y; Ks[t][c+2] = kk4.z; Ks[t][c+3] = kk4.w;
            float4 vv4 = *(const float4*)&V[kb + c];
            Vs[t][c] = vv4.x; Vs[t][c+1] = vv4.y; Vs[t][c+2] = vv4.z; Vs[t][c+3] = vv4.w;
        }
    }
    int rq = wh*8 + (t >> 3), cq = ww*8 + (t & 7);
    size_t qb = ((size_t)(n*Hq + rq)*Wq + cq) * CCH + head*DH;
    float q[DH];
    #pragma unroll
    for (int c = 0; c < DH; c++) q[c] = Q[qb + c];
    __syncthreads();

    const float scale = 0.17677669529663687f;  // 1/sqrt(32)
    float s[64];
    float mx = -1e30f;
    #pragma unroll
    for (int j = 0; j < 64; j++) {
        float d = 0.f;
        #pragma unroll
        for (int c = 0; c < DH; c++) d += q[c] * Ks[j][c];
        d *= scale;
        s[j] = d;
        mx = fmaxf(mx, d);
    }
    float sum = 0.f;
    #pragma unroll
    for (int j = 0; j < 64; j++) { s[j] = __expf(s[j] - mx); sum += s[j]; }
    float inv = 1.f / sum;
    #pragma unroll
    for (int c = 0; c < DH; c++) {
        float acc = 0.f;
        #pragma unroll
        for (int j = 0; j < 64; j++) acc += s[j] * Vs[j][c];
        O[qb + c] = acc * inv;
    }
}

// ---------------- fused residual-add + layernorm (C=256) -----------------
__global__ void add_ln_k(const float* __restrict__ X, const float* __restrict__ P,
                         const float* __restrict__ g, const float* __restrict__ b,
                         float* __restrict__ out) {
    int tok = blockIdx.x;
    int c   = threadIdx.x;
    size_t idx = (size_t)tok * CCH + c;
    float v = X[idx] + P[idx];

    __shared__ float red[8];
    float s = v;
    #pragma unroll
    for (int o = 16; o; o >>= 1) s += __shfl_xor_sync(0xffffffffu, s, o);
    if ((c & 31) == 0) red[c >> 5] = s;
    __syncthreads();
    float mu = 0.f;
    #pragma unroll
    for (int i = 0; i < 8; i++) mu += red[i];
    mu *= (1.f / CCH);

    float d  = v - mu;
    float s2 = d * d;
    #pragma unroll
    for (int o = 16; o; o >>= 1) s2 += __shfl_xor_sync(0xffffffffu, s2, o);
    __syncthreads();
    if ((c & 31) == 0) red[c >> 5] = s2;
    __syncthreads();
    float var = 0.f;
    #pragma unroll
    for (int i = 0; i < 8; i++) var += red[i];
    var *= (1.f / CCH);

    out[idx] = d * rsqrtf(var + 1e-5f) * g[c] + b[c];
}

// ---------------- 4x4 average pool (128x128 -> 32x32) --------------------
__global__ void avgpool_k(const float* __restrict__ in, float* __restrict__ out) {
    int i = blockIdx.x * blockDim.x + threadIdx.x;
    if (i >= TOK1 * CCH) return;
    int c    = i & (CCH - 1);
    int toko = i >> 8;
    int ow = toko & 31; int t = toko >> 5;
    int oh = t & 31;    int n = t >> 5;
    float s = 0.f;
    #pragma unroll
    for (int di = 0; di < 4; di++)
        #pragma unroll
        for (int dj = 0; dj < 4; dj++)
            s += in[((size_t)(n*HH + oh*4 + di)*WW2 + ow*4 + dj)*CCH + c];
    out[i] = s * (1.f / 16.f);
}

// ---------------- host orchestration -------------------------------------
static inline void run_gemm(const float* A, const float* B, const float* bias,
                            float* C, int M, int N, int K, bool relu) {
    dim3 grid(N / 128, M / 128);
    if (relu)       gemm128_k<true,  true ><<<grid, 256>>>(A, B, bias, C, M, N, K);
    else if (bias)  gemm128_k<false, true ><<<grid, 256>>>(A, B, bias, C, M, N, K);
    else            gemm128_k<false, false><<<grid, 256>>>(A, B, bias, C, M, N, K);
}

extern "C" void kernel_launch(void* const* d_in, const int* in_sizes, int n_in,
                              void* d_out, int out_size) {
    const float* x        = (const float*)d_in[0];
    const float* sa_wq    = (const float*)d_in[1];
    const float* sa_wk    = (const float*)d_in[2];
    const float* sa_wv    = (const float*)d_in[3];
    const float* sa_wf    = (const float*)d_in[4];
    const float* sa_bf    = (const float*)d_in[5];
    const float* ca_wq    = (const float*)d_in[6];
    const float* ca_wk    = (const float*)d_in[7];
    const float* ca_wv    = (const float*)d_in[8];
    const float* ca_wf    = (const float*)d_in[9];
    const float* ca_bf    = (const float*)d_in[10];
    const float* ln_s_g   = (const float*)d_in[11];
    const float* ln_s_b   = (const float*)d_in[12];
    const float* ln_c_g   = (const float*)d_in[13];
    const float* ln_c_b   = (const float*)d_in[14];
    const float* ffn_w1   = (const float*)d_in[15];
    const float* ffn_b1   = (const float*)d_in[16];
    const float* ffn_w2   = (const float*)d_in[17];
    const float* ffn_b2   = (const float*)d_in[18];
    const float* ln_o_g   = (const float*)d_in[19];
    const float* ln_o_b   = (const float*)d_in[20];

    float *xh, *q, *k, *v, *attn, *proj, *l0, *lc, *hid;
    float *pool, *q1, *k1, *v1, *a1, *p1, *l1;
    cudaGetSymbolAddress((void**)&xh,   g_xh);
    cudaGetSymbolAddress((void**)&q,    g_q);
    cudaGetSymbolAddress((void**)&k,    g_k);
    cudaGetSymbolAddress((void**)&v,    g_v);
    cudaGetSymbolAddress((void**)&attn, g_attn);
    cudaGetSymbolAddress((void**)&proj, g_proj);
    cudaGetSymbolAddress((void**)&l0,   g_l0);
    cudaGetSymbolAddress((void**)&lc,   g_lc);
    cudaGetSymbolAddress((void**)&hid,  g_hid);
    cudaGetSymbolAddress((void**)&pool, g_pool);
    cudaGetSymbolAddress((void**)&q1,   g_q1);
    cudaGetSymbolAddress((void**)&k1,   g_k1);
    cudaGetSymbolAddress((void**)&v1,   g_v1);
    cudaGetSymbolAddress((void**)&a1,   g_a1);
    cudaGetSymbolAddress((void**)&p1,   g_p1);
    cudaGetSymbolAddress((void**)&l1,   g_l1);

    dim3 tb(32, 8);
    // NCHW -> NHWC
    transpose_in_k<<<dim3(HWP/32, CCH/32, NB), tb>>>(x, xh);

    // ---- level-0 self-attention (128x128) ----
    run_gemm(xh, sa_wq, nullptr, q, TOK0, CCH, CCH, false);
    run_gemm(xh, sa_wk, nullptr, k, TOK0, CCH, CCH, false);
    run_gemm(xh, sa_wv, nullptr, v, TOK0, CCH, CCH, false);
    attn_win_k<<<dim3(NB*16*16, HEADS), 64>>>(q, k, v, attn, HH, WW2, HH, WW2, 8);
    run_gemm(attn, sa_wf, sa_bf, proj, TOK0, CCH, CCH, false);
    add_ln_k<<<TOK0, CCH>>>(xh, proj, ln_s_g, ln_s_b, l0);

    // ---- pool to 32x32 ----
    avgpool_k<<<(TOK1*CCH + 255)/256, 256>>>(l0, pool);

    // ---- level-1 self-attention (32x32) ----
    run_gemm(pool, sa_wq, nullptr, q1, TOK1, CCH, CCH, false);
    run_gemm(pool, sa_wk, nullptr, k1, TOK1, CCH, CCH, false);
    run_gemm(pool, sa_wv, nullptr, v1, TOK1, CCH, CCH, false);
    attn_win_k<<<dim3(NB*4*4, HEADS), 64>>>(q1, k1, v1, a1, H1, H1, H1, H1, 8);
    run_gemm(a1, sa_wf, sa_bf, p1, TOK1, CCH, CCH, false);
    add_ln_k<<<TOK1, CCH>>>(pool, p1, ln_s_g, ln_s_b, l1);

    // ---- cross-attention: q = l0 (128x128), kv = l1 (32x32, stride-2 circular)
    run_gemm(l0, ca_wq, nullptr, q,  TOK0, CCH, CCH, false);
    run_gemm(l1, ca_wk, nullptr, k1, TOK1, CCH, CCH, false);
    run_gemm(l1, ca_wv, nullptr, v1, TOK1, CCH, CCH, false);
    attn_win_k<<<dim3(NB*16*16, HEADS), 64>>>(q, k1, v1, attn, HH, WW2, H1, H1, 2);
    run_gemm(attn, ca_wf, ca_bf, proj, TOK0, CCH, CCH, false);
    add_ln_k<<<TOK0, CCH>>>(l0, proj, ln_c_g, ln_c_b, lc);

    // ---- FFN 256 -> 1024 (relu) -> 256, then residual + LN ----
    run_gemm(lc,  ffn_w1, ffn_b1, hid,  TOK0, DF,  CCH, true);
    run_gemm(hid, ffn_w2, ffn_b2, proj, TOK0, CCH, DF,  false);
    add_ln_k<<<TOK0, CCH>>>(lc, proj, ln_o_g, ln_o_b, attn);

    // NHWC -> NCHW
    transpose_out_k<<<dim3(HWP/32, CCH/32, NB), tb>>>(attn, (float*)d_out);
}

// round 9
// speedup vs baseline: 2.2984x; 1.6394x over previous
#include <cuda_runtime.h>
#include <cuda_bf16.h>
#include <math.h>

// ---------------- problem constants ----------------
#define NB    8
#define CCH   256
#define HH    128
#define WW2   128
#define HWP   (HH*WW2)          // 16384
#define TOK0  (NB*HH*WW2)       // 131072 tokens level-0
#define H1    32
#define TOK1  (NB*H1*H1)        // 8192 tokens level-1
#define HEADS 8
#define DH    32
#define DF    1024

// ---------------- device scratch (static; allocation-free) ----------------
__device__ float g_xh   [(size_t)TOK0*CCH];
__device__ float g_q    [(size_t)TOK0*CCH];
__device__ float g_k    [(size_t)TOK0*CCH];
__device__ float g_v    [(size_t)TOK0*CCH];
__device__ float g_attn [(size_t)TOK0*CCH];
__device__ float g_proj [(size_t)TOK0*CCH];
__device__ float g_l0   [(size_t)TOK0*CCH];
__device__ float g_lc   [(size_t)TOK0*CCH];
__device__ float g_hid  [(size_t)TOK0*DF];
__device__ float g_pool [(size_t)TOK1*CCH];
__device__ float g_q1   [(size_t)TOK1*CCH];
__device__ float g_k1   [(size_t)TOK1*CCH];
__device__ float g_v1   [(size_t)TOK1*CCH];
__device__ float g_a1   [(size_t)TOK1*CCH];
__device__ float g_p1   [(size_t)TOK1*CCH];
__device__ float g_l1   [(size_t)TOK1*CCH];

// ---------------- transposes (NCHW <-> NHWC) ----------------
__global__ void transpose_in_k(const float* __restrict__ in, float* __restrict__ out) {
    __shared__ float tile[32][33];
    int n  = blockIdx.z;
    int p0 = blockIdx.x * 32;
    int c0 = blockIdx.y * 32;
    for (int j = threadIdx.y; j < 32; j += 8)
        tile[j][threadIdx.x] = in[((size_t)(n*CCH + c0 + j))*HWP + p0 + threadIdx.x];
    __syncthreads();
    for (int j = threadIdx.y; j < 32; j += 8)
        out[((size_t)(n*HWP + p0 + j))*CCH + c0 + threadIdx.x] = tile[threadIdx.x][j];
}

__global__ void transpose_out_k(const float* __restrict__ in, float* __restrict__ out) {
    __shared__ float tile[32][33];
    int n  = blockIdx.z;
    int p0 = blockIdx.x * 32;
    int c0 = blockIdx.y * 32;
    for (int j = threadIdx.y; j < 32; j += 8)
        tile[j][threadIdx.x] = in[((size_t)(n*HWP + p0 + j))*CCH + c0 + threadIdx.x];
    __syncthreads();
    for (int j = threadIdx.y; j < 32; j += 8)
        out[((size_t)(n*CCH + c0 + j))*HWP + p0 + threadIdx.x] = tile[threadIdx.x][j];
}

// ---------------- bf16x3 split-precision tensor-core GEMM ------------------
// C[M,N] = A[M,K] @ B[K,N] (+bias)(+relu), fp32-accurate via bf16 hi/lo split:
//   a*b ~= ah*bh + ah*bl + al*bh   (drops al*bl ~ 2^-18 relative)
// Block 128x128xBK16, 256 threads, 8 warps of 32x64 warp-tiles,
// mma.sync.m16n8k16.bf16, ldmatrix for fragments. M%128==0, N%128==0, K%16==0.

#define LDSM_X4(r, addr) \
    asm volatile("ldmatrix.sync.aligned.m8n8.x4.shared.b16 {%0,%1,%2,%3}, [%4];" \
        : "=r"(r[0]), "=r"(r[1]), "=r"(r[2]), "=r"(r[3]) : "r"(addr))

#define LDSM_X4_T(r, addr) \
    asm volatile("ldmatrix.sync.aligned.m8n8.x4.trans.shared.b16 {%0,%1,%2,%3}, [%4];" \
        : "=r"(r[0]), "=r"(r[1]), "=r"(r[2]), "=r"(r[3]) : "r"(addr))

#define MMA_BF16(d, a, b0_, b1_) \
    asm volatile("mma.sync.aligned.m16n8k16.row.col.f32.bf16.bf16.f32 " \
        "{%0,%1,%2,%3}, {%4,%5,%6,%7}, {%8,%9}, {%0,%1,%2,%3};" \
        : "+f"(d[0]), "+f"(d[1]), "+f"(d[2]), "+f"(d[3]) \
        : "r"(a[0]), "r"(a[1]), "r"(a[2]), "r"(a[3]), "r"(b0_), "r"(b1_))

__device__ __forceinline__ void bsplit(float x, __nv_bfloat16& h, __nv_bfloat16& l) {
    h = __float2bfloat16(x);
    l = __float2bfloat16(x - __bfloat162float(h));
}

#define A_STRIDE 24    // 16 used + 8 pad bf16 -> 48B rows, conflict-free ldmatrix
#define B_STRIDE 136   // 128 used + 8 pad bf16 -> 272B rows, conflict-free ldmatrix.trans

template<bool RELU, bool BIAS>
__global__ __launch_bounds__(256, 2)
void gemm_mma_k(const float* __restrict__ A, const float* __restrict__ B,
                const float* __restrict__ bias, float* __restrict__ C,
                int M, int N, int K) {
    __shared__ __align__(16) __nv_bfloat16 Ah[128][A_STRIDE];
    __shared__ __align__(16) __nv_bfloat16 Al[128][A_STRIDE];
    __shared__ __align__(16) __nv_bfloat16 Bh[16][B_STRIDE];
    __shared__ __align__(16) __nv_bfloat16 Bl[16][B_STRIDE];

    int tid  = threadIdx.x;
    int lane = tid & 31;
    int wid  = tid >> 5;
    int m0 = blockIdx.y * 128, n0b = blockIdx.x * 128;

    // warp tile: 32 rows x 64 cols
    int rm = (wid & 3) * 32;        // warp row base within block
    int rn = (wid >> 2) * 64;       // warp col base within block

    // global staging mapping (same as fp32 version)
    int ar = tid >> 2;              // 0..63  (rows ar, ar+64)
    int ak = (tid & 3) * 4;         // 0,4,8,12
    int br = tid >> 5;              // 0..7   (rows br, br+8)
    int bc = (tid & 31) * 4;        // 0..124

    const float* Aptr = A + (size_t)(m0 + ar) * K + ak;
    const float* Bptr = B + (size_t)br * N + n0b + bc;
    const size_t a64 = (size_t)64 * K;
    const size_t b8  = (size_t)8 * N;

    // ldmatrix lane addressing
    int lr  = lane & 15;            // row within 16-tile
    int lc8 = (lane >> 4) * 8;      // 0 or 8 (k-half / n-half)

    float acc[2][8][4];
    #pragma unroll
    for (int i = 0; i < 2; i++)
        #pragma unroll
        for (int j = 0; j < 8; j++)
            #pragma unroll
            for (int r = 0; r < 4; r++) acc[i][j][r] = 0.f;

    float4 pa0 = *(const float4*)(Aptr);
    float4 pa1 = *(const float4*)(Aptr + a64);
    float4 pb0 = *(const float4*)(Bptr);
    float4 pb1 = *(const float4*)(Bptr + b8);

    int chunks = K >> 4;
    for (int ch = 0; ch < chunks; ch++) {
        // ---- stage + split to smem ----
        {
            __nv_bfloat16 h0,l0,h1,l1,h2,l2,h3,l3;
            bsplit(pa0.x,h0,l0); bsplit(pa0.y,h1,l1); bsplit(pa0.z,h2,l2); bsplit(pa0.w,h3,l3);
            __nv_bfloat162 t;
            t.x=h0; t.y=h1; *(__nv_bfloat162*)&Ah[ar][ak]   = t;
            t.x=h2; t.y=h3; *(__nv_bfloat162*)&Ah[ar][ak+2] = t;
            t.x=l0; t.y=l1; *(__nv_bfloat162*)&Al[ar][ak]   = t;
            t.x=l2; t.y=l3; *(__nv_bfloat162*)&Al[ar][ak+2] = t;
            bsplit(pa1.x,h0,l0); bsplit(pa1.y,h1,l1); bsplit(pa1.z,h2,l2); bsplit(pa1.w,h3,l3);
            t.x=h0; t.y=h1; *(__nv_bfloat162*)&Ah[ar+64][ak]   = t;
            t.x=h2; t.y=h3; *(__nv_bfloat162*)&Ah[ar+64][ak+2] = t;
            t.x=l0; t.y=l1; *(__nv_bfloat162*)&Al[ar+64][ak]   = t;
            t.x=l2; t.y=l3; *(__nv_bfloat162*)&Al[ar+64][ak+2] = t;
            bsplit(pb0.x,h0,l0); bsplit(pb0.y,h1,l1); bsplit(pb0.z,h2,l2); bsplit(pb0.w,h3,l3);
            t.x=h0; t.y=h1; *(__nv_bfloat162*)&Bh[br][bc]   = t;
            t.x=h2; t.y=h3; *(__nv_bfloat162*)&Bh[br][bc+2] = t;
            t.x=l0; t.y=l1; *(__nv_bfloat162*)&Bl[br][bc]   = t;
            t.x=l2; t.y=l3; *(__nv_bfloat162*)&Bl[br][bc+2] = t;
            bsplit(pb1.x,h0,l0); bsplit(pb1.y,h1,l1); bsplit(pb1.z,h2,l2); bsplit(pb1.w,h3,l3);
            t.x=h0; t.y=h1; *(__nv_bfloat162*)&Bh[br+8][bc]   = t;
            t.x=h2; t.y=h3; *(__nv_bfloat162*)&Bh[br+8][bc+2] = t;
            t.x=l0; t.y=l1; *(__nv_bfloat162*)&Bl[br+8][bc]   = t;
            t.x=l2; t.y=l3; *(__nv_bfloat162*)&Bl[br+8][bc+2] = t;
        }
        __syncthreads();

        if (ch + 1 < chunks) {   // prefetch next global tile
            Aptr += 16;
            Bptr += (size_t)16 * N;
            pa0 = *(const float4*)(Aptr);
            pa1 = *(const float4*)(Aptr + a64);
            pb0 = *(const float4*)(Bptr);
            pb1 = *(const float4*)(Bptr + b8);
        }

        // ---- A fragments (2 m-tiles x hi/lo) ----
        unsigned a_h[2][4], a_l[2][4];
        #pragma unroll
        for (int mi = 0; mi < 2; mi++) {
            unsigned ad = (unsigned)__cvta_generic_to_shared(&Ah[rm + 16*mi + lr][lc8]);
            LDSM_X4(a_h[mi], ad);
            ad = (unsigned)__cvta_generic_to_shared(&Al[rm + 16*mi + lr][lc8]);
            LDSM_X4(a_l[mi], ad);
        }

        // ---- loop over n-tile pairs: B frags + mma ----
        #pragma unroll
        for (int np = 0; np < 4; np++) {
            int ncol = rn + np * 16;
            unsigned b_h[4], b_l[4];
            unsigned bd = (unsigned)__cvta_generic_to_shared(&Bh[lr][ncol + lc8]);
            LDSM_X4_T(b_h, bd);
            bd = (unsigned)__cvta_generic_to_shared(&Bl[lr][ncol + lc8]);
            LDSM_X4_T(b_l, bd);
            #pragma unroll
            for (int mi = 0; mi < 2; mi++) {
                float* d0 = acc[mi][2*np];
                float* d1 = acc[mi][2*np + 1];
                MMA_BF16(d0, a_h[mi], b_h[0], b_h[1]);
                MMA_BF16(d0, a_h[mi], b_l[0], b_l[1]);
                MMA_BF16(d0, a_l[mi], b_h[0], b_h[1]);
                MMA_BF16(d1, a_h[mi], b_h[2], b_h[3]);
                MMA_BF16(d1, a_h[mi], b_l[2], b_l[3]);
                MMA_BF16(d1, a_l[mi], b_h[2], b_h[3]);
            }
        }
        __syncthreads();
    }

    // ---- epilogue ----
    int g  = lane >> 2;
    int t2 = (lane & 3) * 2;
    #pragma unroll
    for (int mi = 0; mi < 2; mi++) {
        #pragma unroll
        for (int ni = 0; ni < 8; ni++) {
            int col = n0b + rn + 8*ni + t2;
            size_t r0 = (size_t)(m0 + rm + 16*mi + g);
            size_t r1 = r0 + 8;
            float v0 = acc[mi][ni][0], v1 = acc[mi][ni][1];
            float v2 = acc[mi][ni][2], v3 = acc[mi][ni][3];
            if (BIAS) { float b0 = bias[col], b1 = bias[col+1]; v0 += b0; v1 += b1; v2 += b0; v3 += b1; }
            if (RELU) { v0 = fmaxf(v0,0.f); v1 = fmaxf(v1,0.f); v2 = fmaxf(v2,0.f); v3 = fmaxf(v3,0.f); }
            float2 p01 = make_float2(v0, v1);
            float2 p23 = make_float2(v2, v3);
            *(float2*)&C[r0*N + col] = p01;
            *(float2*)&C[r1*N + col] = p23;
        }
    }
}

// ---------------- fused windowed attention -----------------------------
__global__ void attn_win_k(const float* __restrict__ Q, const float* __restrict__ K,
                           const float* __restrict__ V, float* __restrict__ O,
                           int Hq, int Wq, int Hk, int Wk, int strideK) {
    int wW = Wq >> 3, wH = Hq >> 3;
    int b    = blockIdx.x;
    int head = blockIdx.y;
    int ww = b % wW; int t1 = b / wW;
    int wh = t1 % wH; int n  = t1 / wH;
    int t = threadIdx.x;

    __shared__ float Ks[64][33];
    __shared__ float Vs[64][33];

    {
        int ki = t >> 3, kj = t & 7;
        int rk = (wh * strideK + ki) % Hk;
        int ck = (ww * strideK + kj) % Wk;
        size_t kb = ((size_t)(n*Hk + rk)*Wk + ck) * CCH + head*DH;
        #pragma unroll
        for (int c = 0; c < DH; c += 4) {
            float4 kk4 = *(const float4*)&K[kb + c];
            Ks[t][c] = kk4.x; Ks[t][c+1] = kk4.y; Ks[t][c+2] = kk4.z; Ks[t][c+3] = kk4.w;
            float4 vv4 = *(const float4*)&V[kb + c];
            Vs[t][c] = vv4.x; Vs[t][c+1] = vv4.y; Vs[t][c+2] = vv4.z; Vs[t][c+3] = vv4.w;
        }
    }
    int rq = wh*8 + (t >> 3), cq = ww*8 + (t & 7);
    size_t qb = ((size_t)(n*Hq + rq)*Wq + cq) * CCH + head*DH;
    float q[DH];
    #pragma unroll
    for (int c = 0; c < DH; c++) q[c] = Q[qb + c];
    __syncthreads();

    const float scale = 0.17677669529663687f;  // 1/sqrt(32)
    float s[64];
    float mx = -1e30f;
    #pragma unroll
    for (int j = 0; j < 64; j++) {
        float d = 0.f;
        #pragma unroll
        for (int c = 0; c < DH; c++) d += q[c] * Ks[j][c];
        d *= scale;
        s[j] = d;
        mx = fmaxf(mx, d);
    }
    float sum = 0.f;
    #pragma unroll
    for (int j = 0; j < 64; j++) { s[j] = __expf(s[j] - mx); sum += s[j]; }
    float inv = 1.f / sum;
    #pragma unroll
    for (int c = 0; c < DH; c++) {
        float acc = 0.f;
        #pragma unroll
        for (int j = 0; j < 64; j++) acc += s[j] * Vs[j][c];
        O[qb + c] = acc * inv;
    }
}

// ---------------- fused residual-add + layernorm (C=256) -----------------
__global__ void add_ln_k(const float* __restrict__ X, const float* __restrict__ P,
                         const float* __restrict__ g, const float* __restrict__ b,
                         float* __restrict__ out) {
    int tok = blockIdx.x;
    int c   = threadIdx.x;
    size_t idx = (size_t)tok * CCH + c;
    float v = X[idx] + P[idx];

    __shared__ float red[8];
    float s = v;
    #pragma unroll
    for (int o = 16; o; o >>= 1) s += __shfl_xor_sync(0xffffffffu, s, o);
    if ((c & 31) == 0) red[c >> 5] = s;
    __syncthreads();
    float mu = 0.f;
    #pragma unroll
    for (int i = 0; i < 8; i++) mu += red[i];
    mu *= (1.f / CCH);

    float d  = v - mu;
    float s2 = d * d;
    #pragma unroll
    for (int o = 16; o; o >>= 1) s2 += __shfl_xor_sync(0xffffffffu, s2, o);
    __syncthreads();
    if ((c & 31) == 0) red[c >> 5] = s2;
    __syncthreads();
    float var = 0.f;
    #pragma unroll
    for (int i = 0; i < 8; i++) var += red[i];
    var *= (1.f / CCH);

    out[idx] = d * rsqrtf(var + 1e-5f) * g[c] + b[c];
}

// ---------------- 4x4 average pool (128x128 -> 32x32) --------------------
__global__ void avgpool_k(const float* __restrict__ in, float* __restrict__ out) {
    int i = blockIdx.x * blockDim.x + threadIdx.x;
    if (i >= TOK1 * CCH) return;
    int c    = i & (CCH - 1);
    int toko = i >> 8;
    int ow = toko & 31; int t = toko >> 5;
    int oh = t & 31;    int n = t >> 5;
    float s = 0.f;
    #pragma unroll
    for (int di = 0; di < 4; di++)
        #pragma unroll
        for (int dj = 0; dj < 4; dj++)
            s += in[((size_t)(n*HH + oh*4 + di)*WW2 + ow*4 + dj)*CCH + c];
    out[i] = s * (1.f / 16.f);
}

// ---------------- host orchestration -------------------------------------
static inline void run_gemm(const float* A, const float* B, const float* bias,
                            float* C, int M, int N, int K, bool relu) {
    dim3 grid(N / 128, M / 128);
    if (relu)       gemm_mma_k<true,  true ><<<grid, 256>>>(A, B, bias, C, M, N, K);
    else if (bias)  gemm_mma_k<false, true ><<<grid, 256>>>(A, B, bias, C, M, N, K);
    else            gemm_mma_k<false, false><<<grid, 256>>>(A, B, bias, C, M, N, K);
}

extern "C" void kernel_launch(void* const* d_in, const int* in_sizes, int n_in,
                              void* d_out, int out_size) {
    const float* x        = (const float*)d_in[0];
    const float* sa_wq    = (const float*)d_in[1];
    const float* sa_wk    = (const float*)d_in[2];
    const float* sa_wv    = (const float*)d_in[3];
    const float* sa_wf    = (const float*)d_in[4];
    const float* sa_bf    = (const float*)d_in[5];
    const float* ca_wq    = (const float*)d_in[6];
    const float* ca_wk    = (const float*)d_in[7];
    const float* ca_wv    = (const float*)d_in[8];
    const float* ca_wf    = (const float*)d_in[9];
    const float* ca_bf    = (const float*)d_in[10];
    const float* ln_s_g   = (const float*)d_in[11];
    const float* ln_s_b   = (const float*)d_in[12];
    const float* ln_c_g   = (const float*)d_in[13];
    const float* ln_c_b   = (const float*)d_in[14];
    const float* ffn_w1   = (const float*)d_in[15];
    const float* ffn_b1   = (const float*)d_in[16];
    const float* ffn_w2   = (const float*)d_in[17];
    const float* ffn_b2   = (const float*)d_in[18];
    const float* ln_o_g   = (const float*)d_in[19];
    const float* ln_o_b   = (const float*)d_in[20];

    float *xh, *q, *k, *v, *attn, *proj, *l0, *lc, *hid;
    float *pool, *q1, *k1, *v1, *a1, *p1, *l1;
    cudaGetSymbolAddress((void**)&xh,   g_xh);
    cudaGetSymbolAddress((void**)&q,    g_q);
    cudaGetSymbolAddress((void**)&k,    g_k);
    cudaGetSymbolAddress((void**)&v,    g_v);
    cudaGetSymbolAddress((void**)&attn, g_attn);
    cudaGetSymbolAddress((void**)&proj, g_proj);
    cudaGetSymbolAddress((void**)&l0,   g_l0);
    cudaGetSymbolAddress((void**)&lc,   g_lc);
    cudaGetSymbolAddress((void**)&hid,  g_hid);
    cudaGetSymbolAddress((void**)&pool, g_pool);
    cudaGetSymbolAddress((void**)&q1,   g_q1);
    cudaGetSymbolAddress((void**)&k1,   g_k1);
    cudaGetSymbolAddress((void**)&v1,   g_v1);
    cudaGetSymbolAddress((void**)&a1,   g_a1);
    cudaGetSymbolAddress((void**)&p1,   g_p1);
    cudaGetSymbolAddress((void**)&l1,   g_l1);

    dim3 tb(32, 8);
    // NCHW -> NHWC
    transpose_in_k<<<dim3(HWP/32, CCH/32, NB), tb>>>(x, xh);

    // ---- level-0 self-attention (128x128) ----
    run_gemm(xh, sa_wq, nullptr, q, TOK0, CCH, CCH, false);
    run_gemm(xh, sa_wk, nullptr, k, TOK0, CCH, CCH, false);
    run_gemm(xh, sa_wv, nullptr, v, TOK0, CCH, CCH, false);
    attn_win_k<<<dim3(NB*16*16, HEADS), 64>>>(q, k, v, attn, HH, WW2, HH, WW2, 8);
    run_gemm(attn, sa_wf, sa_bf, proj, TOK0, CCH, CCH, false);
    add_ln_k<<<TOK0, CCH>>>(xh, proj, ln_s_g, ln_s_b, l0);

    // ---- pool to 32x32 ----
    avgpool_k<<<(TOK1*CCH + 255)/256, 256>>>(l0, pool);

    // ---- level-1 self-attention (32x32) ----
    run_gemm(pool, sa_wq, nullptr, q1, TOK1, CCH, CCH, false);
    run_gemm(pool, sa_wk, nullptr, k1, TOK1, CCH, CCH, false);
    run_gemm(pool, sa_wv, nullptr, v1, TOK1, CCH, CCH, false);
    attn_win_k<<<dim3(NB*4*4, HEADS), 64>>>(q1, k1, v1, a1, H1, H1, H1, H1, 8);
    run_gemm(a1, sa_wf, sa_bf, p1, TOK1, CCH, CCH, false);
    add_ln_k<<<TOK1, CCH>>>(pool, p1, ln_s_g, ln_s_b, l1);

    // ---- cross-attention: q = l0 (128x128), kv = l1 (32x32, stride-2 circular)
    run_gemm(l0, ca_wq, nullptr, q,  TOK0, CCH, CCH, false);
    run_gemm(l1, ca_wk, nullptr, k1, TOK1, CCH, CCH, false);
    run_gemm(l1, ca_wv, nullptr, v1, TOK1, CCH, CCH, false);
    attn_win_k<<<dim3(NB*16*16, HEADS), 64>>>(q, k1, v1, attn, HH, WW2, H1, H1, 2);
    run_gemm(attn, ca_wf, ca_bf, proj, TOK0, CCH, CCH, false);
    add_ln_k<<<TOK0, CCH>>>(l0, proj, ln_c_g, ln_c_b, lc);

    // ---- FFN 256 -> 1024 (relu) -> 256, then residual + LN ----
    run_gemm(lc,  ffn_w1, ffn_b1, hid,  TOK0, DF,  CCH, true);
    run_gemm(hid, ffn_w2, ffn_b2, proj, TOK0, CCH, DF,  false);
    add_ln_k<<<TOK0, CCH>>>(lc, proj, ln_o_g, ln_o_b, attn);

    // NHWC -> NCHW
    transpose_out_k<<<dim3(HWP/32, CCH/32, NB), tb>>>(attn, (float*)d_out);
}